// round 15
// baseline (speedup 1.0000x reference)
#include <cuda_runtime.h>
#include <cuda_pipeline.h>
#include <cuda_bf16.h>
#include <cstdint>

#define BB 8
#define SS 2048
#define DD 768
#define NSP 512
#define MAXW 30
#define HH 100
#define M_TOTAL (BB*NSP)   /* 4096 */
#define NPAD 112

__device__ float g_logits[BB*SS];
__device__ __nv_bfloat16 g_att_hi[(size_t)M_TOTAL*DD];
__device__ __nv_bfloat16 g_att_lo[(size_t)M_TOTAL*DD];
__device__ __nv_bfloat16 g_wt_hi[(size_t)NPAD*DD];
__device__ __nv_bfloat16 g_wt_lo[(size_t)NPAD*DD];
__device__ float g_part[2][(size_t)M_TOTAL*NPAD];

typedef unsigned long long ull;

__device__ __forceinline__ void f32x2_fma(ull& acc, ull a, ull b) {
    asm("fma.rn.f32x2 %0, %1, %2, %0;" : "+l"(acc) : "l"(a), "l"(b));
}
__device__ __forceinline__ float2 f32x2_unpack(ull v) {
    unsigned int lo, hi;
    asm("mov.b64 {%0, %1}, %2;" : "=r"(lo), "=r"(hi) : "l"(v));
    return make_float2(__uint_as_float(lo), __uint_as_float(hi));
}
__device__ __forceinline__ uint32_t smem_to_u32(const void* p) {
    uint32_t a;
    asm("{ .reg .u64 t; cvta.to.shared.u64 t, %1; cvt.u32.u64 %0, t; }" : "=r"(a) : "l"(p));
    return a;
}
__device__ __forceinline__ float tanh_approx(float x) {
    float y;
    asm("tanh.approx.f32 %0, %1;" : "=f"(y) : "f"(x));
    return y;
}
__device__ __forceinline__ void ldmx4(uint32_t* r, uint32_t addr) {
    asm volatile("ldmatrix.sync.aligned.m8n8.x4.shared.b16 {%0,%1,%2,%3}, [%4];"
        : "=r"(r[0]), "=r"(r[1]), "=r"(r[2]), "=r"(r[3]) : "r"(addr));
}
__device__ __forceinline__ void ldmx2(uint32_t* r, uint32_t addr) {
    asm volatile("ldmatrix.sync.aligned.m8n8.x2.shared.b16 {%0,%1}, [%2];"
        : "=r"(r[0]), "=r"(r[1]) : "r"(addr));
}
__device__ __forceinline__ void mma_bf16(float* c, const uint32_t* a, const uint32_t* b) {
    asm volatile("mma.sync.aligned.m16n8k16.row.col.f32.bf16.bf16.f32 "
        "{%0,%1,%2,%3}, {%4,%5,%6,%7}, {%8,%9}, {%0,%1,%2,%3};"
        : "+f"(c[0]), "+f"(c[1]), "+f"(c[2]), "+f"(c[3])
        : "r"(a[0]), "r"(a[1]), "r"(a[2]), "r"(a[3]), "r"(b[0]), "r"(b[1]));
}

// -------- Kernel 0: transpose + bf16-split W into [112 x 768] K-major ----------
__global__ void __launch_bounds__(192) k_wprep(const float* __restrict__ W) {
    int n = blockIdx.x;
    for (int k = threadIdx.x; k < DD; k += 192) {
        float w = (n < HH) ? W[(size_t)k * HH + n] : 0.f;
        __nv_bfloat16 hi = __float2bfloat16(w);
        float lo = w - __bfloat162float(hi);
        g_wt_hi[(size_t)n * DD + k] = hi;
        g_wt_lo[(size_t)n * DD + k] = __float2bfloat16(lo);
    }
}

// -------- Kernel 1: logits via cp.async double-buffered streaming (R9) ---------
__global__ void __launch_bounds__(256) k_logits(const float* __restrict__ seq,
                                                const float* __restrict__ att_w,
                                                const float* __restrict__ att_b) {
    __shared__ float4 sbuf[2][8 * (DD / 4)];

    int tid = threadIdx.x, warp = tid >> 5, lane = tid & 31;
    size_t base = (size_t)blockIdx.x * 32;
    const float4* src = (const float4*)seq + base * (DD / 4);

#pragma unroll
    for (int k = 0; k < 6; k++) {
        int idx = tid + k * 256;
        __pipeline_memcpy_async(&sbuf[0][idx], &src[idx], 16);
    }
    __pipeline_commit();
#pragma unroll
    for (int k = 0; k < 6; k++) {
        int idx = tid + k * 256;
        __pipeline_memcpy_async(&sbuf[1][idx], &src[1536 + idx], 16);
    }
    __pipeline_commit();

    float4 wreg[6];
    const float4* w4 = (const float4*)att_w;
#pragma unroll
    for (int j = 0; j < 6; j++) wreg[j] = __ldg(&w4[lane + 32 * j]);
    float bconst = __ldg(att_b);

    for (int s = 0; s < 4; s++) {
        if (s < 3) __pipeline_wait_prior(1);
        else       __pipeline_wait_prior(0);
        __syncthreads();

        const float4* row = &sbuf[s & 1][warp * (DD / 4)];
        float4 x[6];
#pragma unroll
        for (int j = 0; j < 6; j++) x[j] = row[lane + 32 * j];
        ull acc = 0ull;
#pragma unroll
        for (int j = 0; j < 6; j++) {
            const ull* xp = (const ull*)&x[j];
            const ull* wp = (const ull*)&wreg[j];
            f32x2_fma(acc, xp[0], wp[0]);
            f32x2_fma(acc, xp[1], wp[1]);
        }
        float2 p = f32x2_unpack(acc);
        float sum = p.x + p.y;
#pragma unroll
        for (int o = 16; o > 0; o >>= 1) sum += __shfl_xor_sync(0xffffffffu, sum, o);
        if (lane == 0) g_logits[base + s * 8 + warp] = sum + bconst;
        __syncthreads();

        if (s + 2 < 4) {
            const float4* g = src + (size_t)(s + 2) * 1536;
#pragma unroll
            for (int k = 0; k < 6; k++) {
                int idx = tid + k * 256;
                __pipeline_memcpy_async(&sbuf[s & 1][idx], &g[idx], 16);
            }
            __pipeline_commit();
        }
    }
}

// -------- Kernel 2: span softmax + weighted sum -> bf16 hi/lo -------------------
__global__ void __launch_bounds__(192) k_span(const float* __restrict__ seq,
                                              const int* __restrict__ spans,
                                              const int* __restrict__ mask) {
    __shared__ float s_attn[MAXW];
    __shared__ int   s_start, s_cnt;
    int sp  = blockIdx.x;
    int b   = sp >> 9;
    int tid = threadIdx.x;

    if (tid < 32) {
        int start = spans[sp * 2];
        int cnt   = spans[sp * 2 + 1] - start;
        float lg = (tid < cnt) ? g_logits[b * SS + start + tid] : -1e30f;
        float mx = lg;
#pragma unroll
        for (int o = 16; o > 0; o >>= 1) mx = fmaxf(mx, __shfl_xor_sync(0xffffffffu, mx, o));
        float ex = (tid < cnt) ? expf(lg - mx) : 0.f;
        float sm = ex;
#pragma unroll
        for (int o = 16; o > 0; o >>= 1) sm += __shfl_xor_sync(0xffffffffu, sm, o);
        float mk = (float)mask[sp];
        if (tid < MAXW) s_attn[tid] = ex / sm * mk;
        if (tid == 0) { s_start = start; s_cnt = cnt; }
    }
    __syncthreads();

    int start = s_start, cnt = s_cnt;
    const float4* base = (const float4*)seq + (size_t)(b * SS + start) * (DD / 4) + tid;
    float4 acc = make_float4(0.f, 0.f, 0.f, 0.f);
#pragma unroll 4
    for (int w = 0; w < cnt; w++) {
        float a  = s_attn[w];
        float4 v = base[(size_t)w * (DD / 4)];
        acc.x += a * v.x; acc.y += a * v.y; acc.z += a * v.z; acc.w += a * v.w;
    }

    size_t idx = (size_t)sp * DD + tid * 4;
    __nv_bfloat16 h0 = __float2bfloat16(acc.x);
    __nv_bfloat16 h1 = __float2bfloat16(acc.y);
    __nv_bfloat16 h2 = __float2bfloat16(acc.z);
    __nv_bfloat16 h3 = __float2bfloat16(acc.w);
    *(__nv_bfloat162*)&g_att_hi[idx]     = __halves2bfloat162(h0, h1);
    *(__nv_bfloat162*)&g_att_hi[idx + 2] = __halves2bfloat162(h2, h3);
    __nv_bfloat16 l0 = __float2bfloat16(acc.x - __bfloat162float(h0));
    __nv_bfloat16 l1 = __float2bfloat16(acc.y - __bfloat162float(h1));
    __nv_bfloat16 l2 = __float2bfloat16(acc.z - __bfloat162float(h2));
    __nv_bfloat16 l3 = __float2bfloat16(acc.w - __bfloat162float(h3));
    *(__nv_bfloat162*)&g_att_lo[idx]     = __halves2bfloat162(l0, l1);
    *(__nv_bfloat162*)&g_att_lo[idx + 2] = __halves2bfloat162(l2, l3);
}

// ---- Kernel 3: mma.sync bf16 3-pass GEMM partials, M-tile 64, grid-K=2 --------
// grid = (64, 2), block 512 = 16 warps = (ms 0..3 x nh 0..1 x kh 0..1).
// Per chunk (K=64): warp does 2 ksteps of 16 -> 42 HMMA. 6 chunks per block.
#define AST 144                     /* A/W smem row stride bytes */
#define SM_A_HI 0                   /* 2 bufs x 64 x 144 = 18432 */
#define SM_A_LO 18432
#define SM_W_HI 36864               /* 2 bufs x 112 x 144 = 32256 */
#define SM_W_LO 69120
#define SM_GEMM_TOTAL 101376

__global__ void __launch_bounds__(512) k_gemm(void) {
    extern __shared__ __align__(16) char smem[];
    uint32_t sb = smem_to_u32(smem);
    int tid = threadIdx.x, warp = tid >> 5, lane = tid & 31;
    int ms = warp & 3, nh = (warp >> 2) & 1, kh = warp >> 3;
    int m0 = blockIdx.x * 64;
    int ks = blockIdx.y;
    int kbase = ks * 384;           // this block's K range: [kbase, kbase+384)
    int g = lane >> 2, tk = lane & 3;

    float acc[7][4];
#pragma unroll
    for (int t = 0; t < 7; t++)
#pragma unroll
        for (int q = 0; q < 4; q++) acc[t][q] = 0.f;

    const char* Ahi = (const char*)g_att_hi + ((size_t)m0 * DD + kbase) * 2;
    const char* Alo = (const char*)g_att_lo + ((size_t)m0 * DD + kbase) * 2;
    const char* Whi = (const char*)g_wt_hi + (size_t)kbase * 2;
    const char* Wlo = (const char*)g_wt_lo + (size_t)kbase * 2;

    auto load_chunk = [&](int c, int buf) {
        int koff = c * 64;
        {   // A: 64 rows x 8 pieces of 16B -> 512 threads, 1 each (hi+lo)
            int row = tid >> 3, j = tid & 7;
            size_t so = ((size_t)row * DD + koff + j * 8) * 2;
            uint32_t d = (uint32_t)(buf * 64 * AST + row * AST + j * 16);
            __pipeline_memcpy_async(smem + SM_A_HI + d, Ahi + so, 16);
            __pipeline_memcpy_async(smem + SM_A_LO + d, Alo + so, 16);
        }
        for (int p = tid; p < 896; p += 512) {   // W: 112 rows x 8 pieces
            int row = p >> 3, j = p & 7;
            size_t so = ((size_t)row * DD + koff + j * 8) * 2;
            uint32_t d = (uint32_t)(buf * 112 * AST + row * AST + j * 16);
            __pipeline_memcpy_async(smem + SM_W_HI + d, Whi + so, 16);
            __pipeline_memcpy_async(smem + SM_W_LO + d, Wlo + so, 16);
        }
    };

    int row_in = lane & 15, khf = lane >> 4;
    int brow = lane & 7, bko = (lane & 8) ? 8 : 0;

    auto compute = [&](int buf) {
#pragma unroll
        for (int s = 0; s < 2; s++) {
            int k0 = kh * 32 + s * 16;
            uint32_t addrA = sb + SM_A_HI + buf * 64 * AST
                           + (ms * 16 + row_in) * AST + (k0 + khf * 8) * 2;
            uint32_t ahi[4], alo[4];
            ldmx4(ahi, addrA);
            ldmx4(alo, addrA + (SM_A_LO - SM_A_HI));
#pragma unroll
            for (int t = 0; t < 7; t++) {
                int n0 = (nh * 7 + t) * 8;
                uint32_t addrB = sb + SM_W_HI + buf * 112 * AST
                               + (n0 + brow) * AST + (k0 + bko) * 2;
                uint32_t bhi[2], blo[2];
                ldmx2(bhi, addrB);
                ldmx2(blo, addrB + (SM_W_LO - SM_W_HI));
                mma_bf16(acc[t], ahi, bhi);
                mma_bf16(acc[t], ahi, blo);
                mma_bf16(acc[t], alo, bhi);
            }
        }
    };

    load_chunk(0, 0);
    __pipeline_commit();

    for (int c = 0; c < 6; c++) {
        if (c + 1 < 6) { load_chunk(c + 1, (c + 1) & 1); __pipeline_commit(); }
        if (c + 1 < 6) __pipeline_wait_prior(1);
        else           __pipeline_wait_prior(0);
        __syncthreads();
        compute(c & 1);
        __syncthreads();
    }

    // combine kh pairs through smem: kh=1 dumps, kh=0 adds + writes fp32 partial
    float* sc = (float*)smem;       // 8 groups x 7 tiles x 32 lanes x 4 = 7168 f
    if (kh == 1) {
#pragma unroll
        for (int t = 0; t < 7; t++) {
            int idx = (((ms * 2 + nh) * 7 + t) * 32 + lane) * 4;
            sc[idx + 0] = acc[t][0]; sc[idx + 1] = acc[t][1];
            sc[idx + 2] = acc[t][2]; sc[idx + 3] = acc[t][3];
        }
    }
    __syncthreads();

    if (kh == 0) {
        int row0 = m0 + ms * 16 + g;
        float* part = g_part[ks];
#pragma unroll
        for (int t = 0; t < 7; t++) {
            int n0 = (nh * 7 + t) * 8;
            int col = n0 + tk * 2;
            int idx = (((ms * 2 + nh) * 7 + t) * 32 + lane) * 4;
            float2 v0, v1;
            v0.x = acc[t][0] + sc[idx + 0];
            v0.y = acc[t][1] + sc[idx + 1];
            v1.x = acc[t][2] + sc[idx + 2];
            v1.y = acc[t][3] + sc[idx + 3];
            *(float2*)&part[(size_t)row0 * NPAD + col]       = v0;
            *(float2*)&part[(size_t)(row0 + 8) * NPAD + col] = v1;
        }
    }
}

// -------- Kernel 4: combine K-halves + bias + tanh.approx ----------------------
__global__ void __launch_bounds__(256) k_epi(const float* __restrict__ bias,
                                             float* __restrict__ out) {
    int i = blockIdx.x * 256 + threadIdx.x;        // f4 index over out (114688)
    if (i < M_TOTAL * HH / 4) {
        int o = i * 4;
        int row = o / HH, col = o % HH;            // 100 % 4 == 0: no straddle
        size_t pidx = (size_t)row * NPAD + col;
        float4 a = *(const float4*)&g_part[0][pidx];
        float4 b = *(const float4*)&g_part[1][pidx];
        float4 v;
        v.x = tanh_approx(a.x + b.x + __ldg(&bias[col + 0]));
        v.y = tanh_approx(a.y + b.y + __ldg(&bias[col + 1]));
        v.z = tanh_approx(a.z + b.z + __ldg(&bias[col + 2]));
        v.w = tanh_approx(a.w + b.w + __ldg(&bias[col + 3]));
        ((float4*)out)[i] = v;
    }
}

extern "C" void kernel_launch(void* const* d_in, const int* in_sizes, int n_in,
                              void* d_out, int out_size) {
    const float* seq   = (const float*)d_in[0];
    const int*   spans = (const int*)d_in[1];
    const int*   mask  = (const int*)d_in[2];
    const float* att_w = (const float*)d_in[3];
    const float* att_b = (const float*)d_in[4];
    const float* ffn_w = (const float*)d_in[5];
    const float* ffn_b = (const float*)d_in[6];
    float*       out   = (float*)d_out;

    cudaFuncSetAttribute(k_gemm, cudaFuncAttributeMaxDynamicSharedMemorySize, SM_GEMM_TOTAL);

    k_wprep<<<NPAD, 192>>>(ffn_w);
    k_logits<<<512, 256>>>(seq, att_w, att_b);
    k_span<<<M_TOTAL, 192>>>(seq, spans, mask);
    k_gemm<<<dim3(64, 2), 512, SM_GEMM_TOTAL>>>();
    k_epi<<<(M_TOTAL * HH / 4 + 255) / 256, 256>>>(ffn_b, out);
}

// round 16
// speedup vs baseline: 1.0816x; 1.0816x over previous
#include <cuda_runtime.h>
#include <cuda_pipeline.h>
#include <cuda_bf16.h>
#include <cstdint>

#define BB 8
#define SS 2048
#define DD 768
#define NSP 512
#define MAXW 30
#define HH 100
#define M_TOTAL (BB*NSP)   /* 4096 */
#define NPAD 112

__device__ float g_logits[BB*SS];
__device__ __nv_bfloat16 g_att_hi[(size_t)M_TOTAL*DD];
__device__ __nv_bfloat16 g_att_lo[(size_t)M_TOTAL*DD];
__device__ __nv_bfloat16 g_wt_hi[(size_t)NPAD*DD];
__device__ __nv_bfloat16 g_wt_lo[(size_t)NPAD*DD];

typedef unsigned long long ull;

__device__ __forceinline__ void f32x2_fma(ull& acc, ull a, ull b) {
    asm("fma.rn.f32x2 %0, %1, %2, %0;" : "+l"(acc) : "l"(a), "l"(b));
}
__device__ __forceinline__ float2 f32x2_unpack(ull v) {
    unsigned int lo, hi;
    asm("mov.b64 {%0, %1}, %2;" : "=r"(lo), "=r"(hi) : "l"(v));
    return make_float2(__uint_as_float(lo), __uint_as_float(hi));
}
__device__ __forceinline__ uint32_t smem_to_u32(const void* p) {
    uint32_t a;
    asm("{ .reg .u64 t; cvta.to.shared.u64 t, %1; cvt.u32.u64 %0, t; }" : "=r"(a) : "l"(p));
    return a;
}
__device__ __forceinline__ float tanh_approx(float x) {
    float y;
    asm("tanh.approx.f32 %0, %1;" : "=f"(y) : "f"(x));
    return y;
}
__device__ __forceinline__ void ldmx4(uint32_t* r, uint32_t addr) {
    asm volatile("ldmatrix.sync.aligned.m8n8.x4.shared.b16 {%0,%1,%2,%3}, [%4];"
        : "=r"(r[0]), "=r"(r[1]), "=r"(r[2]), "=r"(r[3]) : "r"(addr));
}
__device__ __forceinline__ void ldmx2(uint32_t* r, uint32_t addr) {
    asm volatile("ldmatrix.sync.aligned.m8n8.x2.shared.b16 {%0,%1}, [%2];"
        : "=r"(r[0]), "=r"(r[1]) : "r"(addr));
}
__device__ __forceinline__ void mma_bf16(float* c, const uint32_t* a, const uint32_t* b) {
    asm volatile("mma.sync.aligned.m16n8k16.row.col.f32.bf16.bf16.f32 "
        "{%0,%1,%2,%3}, {%4,%5,%6,%7}, {%8,%9}, {%0,%1,%2,%3};"
        : "+f"(c[0]), "+f"(c[1]), "+f"(c[2]), "+f"(c[3])
        : "r"(a[0]), "r"(a[1]), "r"(a[2]), "r"(a[3]), "r"(b[0]), "r"(b[1]));
}

// -------- Kernel 0: transpose + bf16-split W into [112 x 768] K-major ----------
__global__ void __launch_bounds__(192) k_wprep(const float* __restrict__ W) {
    int n = blockIdx.x;
    for (int k = threadIdx.x; k < DD; k += 192) {
        float w = (n < HH) ? W[(size_t)k * HH + n] : 0.f;
        __nv_bfloat16 hi = __float2bfloat16(w);
        float lo = w - __bfloat162float(hi);
        g_wt_hi[(size_t)n * DD + k] = hi;
        g_wt_lo[(size_t)n * DD + k] = __float2bfloat16(lo);
    }
}

// -------- Kernel 1: logits via cp.async double-buffered streaming (R9) ---------
__global__ void __launch_bounds__(256) k_logits(const float* __restrict__ seq,
                                                const float* __restrict__ att_w,
                                                const float* __restrict__ att_b) {
    __shared__ float4 sbuf[2][8 * (DD / 4)];

    int tid = threadIdx.x, warp = tid >> 5, lane = tid & 31;
    size_t base = (size_t)blockIdx.x * 32;
    const float4* src = (const float4*)seq + base * (DD / 4);

#pragma unroll
    for (int k = 0; k < 6; k++) {
        int idx = tid + k * 256;
        __pipeline_memcpy_async(&sbuf[0][idx], &src[idx], 16);
    }
    __pipeline_commit();
#pragma unroll
    for (int k = 0; k < 6; k++) {
        int idx = tid + k * 256;
        __pipeline_memcpy_async(&sbuf[1][idx], &src[1536 + idx], 16);
    }
    __pipeline_commit();

    float4 wreg[6];
    const float4* w4 = (const float4*)att_w;
#pragma unroll
    for (int j = 0; j < 6; j++) wreg[j] = __ldg(&w4[lane + 32 * j]);
    float bconst = __ldg(att_b);

    for (int s = 0; s < 4; s++) {
        if (s < 3) __pipeline_wait_prior(1);
        else       __pipeline_wait_prior(0);
        __syncthreads();

        const float4* row = &sbuf[s & 1][warp * (DD / 4)];
        float4 x[6];
#pragma unroll
        for (int j = 0; j < 6; j++) x[j] = row[lane + 32 * j];
        ull acc = 0ull;
#pragma unroll
        for (int j = 0; j < 6; j++) {
            const ull* xp = (const ull*)&x[j];
            const ull* wp = (const ull*)&wreg[j];
            f32x2_fma(acc, xp[0], wp[0]);
            f32x2_fma(acc, xp[1], wp[1]);
        }
        float2 p = f32x2_unpack(acc);
        float sum = p.x + p.y;
#pragma unroll
        for (int o = 16; o > 0; o >>= 1) sum += __shfl_xor_sync(0xffffffffu, sum, o);
        if (lane == 0) g_logits[base + s * 8 + warp] = sum + bconst;
        __syncthreads();

        if (s + 2 < 4) {
            const float4* g = src + (size_t)(s + 2) * 1536;
#pragma unroll
            for (int k = 0; k < 6; k++) {
                int idx = tid + k * 256;
                __pipeline_memcpy_async(&sbuf[s & 1][idx], &g[idx], 16);
            }
            __pipeline_commit();
        }
    }
}

// -------- Kernel 2: span softmax + weighted sum -> bf16 hi/lo -------------------
__global__ void __launch_bounds__(192) k_span(const float* __restrict__ seq,
                                              const int* __restrict__ spans,
                                              const int* __restrict__ mask) {
    __shared__ float s_attn[MAXW];
    __shared__ int   s_start, s_cnt;
    int sp  = blockIdx.x;
    int b   = sp >> 9;
    int tid = threadIdx.x;

    if (tid < 32) {
        int start = spans[sp * 2];
        int cnt   = spans[sp * 2 + 1] - start;
        float lg = (tid < cnt) ? g_logits[b * SS + start + tid] : -1e30f;
        float mx = lg;
#pragma unroll
        for (int o = 16; o > 0; o >>= 1) mx = fmaxf(mx, __shfl_xor_sync(0xffffffffu, mx, o));
        float ex = (tid < cnt) ? expf(lg - mx) : 0.f;
        float sm = ex;
#pragma unroll
        for (int o = 16; o > 0; o >>= 1) sm += __shfl_xor_sync(0xffffffffu, sm, o);
        float mk = (float)mask[sp];
        if (tid < MAXW) s_attn[tid] = ex / sm * mk;
        if (tid == 0) { s_start = start; s_cnt = cnt; }
    }
    __syncthreads();

    int start = s_start, cnt = s_cnt;
    const float4* base = (const float4*)seq + (size_t)(b * SS + start) * (DD / 4) + tid;
    float4 acc = make_float4(0.f, 0.f, 0.f, 0.f);
#pragma unroll 4
    for (int w = 0; w < cnt; w++) {
        float a  = s_attn[w];
        float4 v = base[(size_t)w * (DD / 4)];
        acc.x += a * v.x; acc.y += a * v.y; acc.z += a * v.z; acc.w += a * v.w;
    }

    size_t idx = (size_t)sp * DD + tid * 4;
    __nv_bfloat16 h0 = __float2bfloat16(acc.x);
    __nv_bfloat16 h1 = __float2bfloat16(acc.y);
    __nv_bfloat16 h2 = __float2bfloat16(acc.z);
    __nv_bfloat16 h3 = __float2bfloat16(acc.w);
    *(__nv_bfloat162*)&g_att_hi[idx]     = __halves2bfloat162(h0, h1);
    *(__nv_bfloat162*)&g_att_hi[idx + 2] = __halves2bfloat162(h2, h3);
    __nv_bfloat16 l0 = __float2bfloat16(acc.x - __bfloat162float(h0));
    __nv_bfloat16 l1 = __float2bfloat16(acc.y - __bfloat162float(h1));
    __nv_bfloat16 l2 = __float2bfloat16(acc.z - __bfloat162float(h2));
    __nv_bfloat16 l3 = __float2bfloat16(acc.w - __bfloat162float(h3));
    *(__nv_bfloat162*)&g_att_lo[idx]     = __halves2bfloat162(l0, l1);
    *(__nv_bfloat162*)&g_att_lo[idx + 2] = __halves2bfloat162(l2, l3);
}

// ---- Kernel 3: mma.sync bf16 3-pass GEMM, M-tile 64, grid-N=2, full K ---------
// grid = (64, 2), block 512 = 16 warps = (ms 0..3 x kh 0..3). Each block owns
// 56 output columns and ALL of K -> no cross-block combine. Warp: one 16-wide
// kstep per 64-chunk, 7 n-tiles, 12 chunks -> 252 HMMA. 4-way kh smem combine,
// bias + tanh.approx epilogue written directly to out.
#define AST 144
#define SM_A_HI 0                   /* 2 bufs x 64 x 144 = 18432 */
#define SM_A_LO 18432
#define SM_W_HI 36864               /* 2 bufs x 56 x 144 = 16128 */
#define SM_W_LO 52992
#define SM_GEMM_TOTAL 69120

__global__ void __launch_bounds__(512) k_gemm(const float* __restrict__ bias,
                                              float* __restrict__ out) {
    extern __shared__ __align__(16) char smem[];
    uint32_t sb = smem_to_u32(smem);
    int tid = threadIdx.x, warp = tid >> 5, lane = tid & 31;
    int ms = warp & 3, kh = warp >> 2;           // kh 0..3
    int m0 = blockIdx.x * 64;
    int nbase = blockIdx.y * 56;                 // output-column base
    int g = lane >> 2, tk = lane & 3;

    float acc[7][4];
#pragma unroll
    for (int t = 0; t < 7; t++)
#pragma unroll
        for (int q = 0; q < 4; q++) acc[t][q] = 0.f;

    const char* Ahi = (const char*)g_att_hi + (size_t)m0 * DD * 2;
    const char* Alo = (const char*)g_att_lo + (size_t)m0 * DD * 2;
    const char* Whi = (const char*)g_wt_hi + (size_t)nbase * DD * 2;
    const char* Wlo = (const char*)g_wt_lo + (size_t)nbase * DD * 2;

    auto load_chunk = [&](int c, int buf) {
        int koff = c * 64;
        {   // A: 64 rows x 8 pieces -> 512 threads, one each (hi+lo)
            int row = tid >> 3, j = tid & 7;
            size_t so = ((size_t)row * DD + koff + j * 8) * 2;
            uint32_t d = (uint32_t)(buf * 64 * AST + row * AST + j * 16);
            __pipeline_memcpy_async(smem + SM_A_HI + d, Ahi + so, 16);
            __pipeline_memcpy_async(smem + SM_A_LO + d, Alo + so, 16);
        }
        if (tid < 448) {   // W: 56 rows x 8 pieces
            int row = tid >> 3, j = tid & 7;
            size_t so = ((size_t)row * DD + koff + j * 8) * 2;
            uint32_t d = (uint32_t)(buf * 56 * AST + row * AST + j * 16);
            __pipeline_memcpy_async(smem + SM_W_HI + d, Whi + so, 16);
            __pipeline_memcpy_async(smem + SM_W_LO + d, Wlo + so, 16);
        }
    };

    int row_in = lane & 15, khf = lane >> 4;
    int brow = lane & 7, bko = (lane & 8) ? 8 : 0;

    auto compute = [&](int buf) {
        int k0 = kh * 16;
        uint32_t addrA = sb + SM_A_HI + buf * 64 * AST
                       + (ms * 16 + row_in) * AST + (k0 + khf * 8) * 2;
        uint32_t ahi[4], alo[4];
        ldmx4(ahi, addrA);
        ldmx4(alo, addrA + (SM_A_LO - SM_A_HI));
#pragma unroll
        for (int t = 0; t < 7; t++) {
            int n0 = t * 8;
            uint32_t addrB = sb + SM_W_HI + buf * 56 * AST
                           + (n0 + brow) * AST + (k0 + bko) * 2;
            uint32_t bhi[2], blo[2];
            ldmx2(bhi, addrB);
            ldmx2(blo, addrB + (SM_W_LO - SM_W_HI));
            mma_bf16(acc[t], ahi, bhi);
            mma_bf16(acc[t], ahi, blo);
            mma_bf16(acc[t], alo, bhi);
        }
    };

    load_chunk(0, 0);
    __pipeline_commit();

    for (int c = 0; c < 12; c++) {
        if (c + 1 < 12) { load_chunk(c + 1, (c + 1) & 1); __pipeline_commit(); }
        if (c + 1 < 12) __pipeline_wait_prior(1);
        else            __pipeline_wait_prior(0);
        __syncthreads();
        compute(c & 1);
        __syncthreads();
    }

    // combine 4 kh-partials: kh 1..3 dump to smem, kh=0 sums + tanh + store.
    // groups: 4 ms x 7 t x 32 lanes x 4 floats = 3584 floats per kh.
    float* sc = (float*)smem;
    if (kh > 0) {
        float* dst = sc + (size_t)(kh - 1) * 3584;
#pragma unroll
        for (int t = 0; t < 7; t++) {
            int idx = ((ms * 7 + t) * 32 + lane) * 4;
            dst[idx + 0] = acc[t][0]; dst[idx + 1] = acc[t][1];
            dst[idx + 2] = acc[t][2]; dst[idx + 3] = acc[t][3];
        }
    }
    __syncthreads();

    if (kh == 0) {
        int row0 = m0 + ms * 16 + g;
#pragma unroll
        for (int t = 0; t < 7; t++) {
            int col = nbase + t * 8 + tk * 2;
            if (col < HH) {
                int idx = ((ms * 7 + t) * 32 + lane) * 4;
                float p0 = sc[idx + 0] + sc[3584 + idx + 0] + sc[7168 + idx + 0];
                float p1 = sc[idx + 1] + sc[3584 + idx + 1] + sc[7168 + idx + 1];
                float p2 = sc[idx + 2] + sc[3584 + idx + 2] + sc[7168 + idx + 2];
                float p3 = sc[idx + 3] + sc[3584 + idx + 3] + sc[7168 + idx + 3];
                float b0 = __ldg(&bias[col]), b1 = __ldg(&bias[col + 1]);
                float2 v0, v1;
                v0.x = tanh_approx(acc[t][0] + p0 + b0);
                v0.y = tanh_approx(acc[t][1] + p1 + b1);
                v1.x = tanh_approx(acc[t][2] + p2 + b0);
                v1.y = tanh_approx(acc[t][3] + p3 + b1);
                *(float2*)&out[(size_t)row0 * HH + col]       = v0;
                *(float2*)&out[(size_t)(row0 + 8) * HH + col] = v1;
            }
        }
    }
}

extern "C" void kernel_launch(void* const* d_in, const int* in_sizes, int n_in,
                              void* d_out, int out_size) {
    const float* seq   = (const float*)d_in[0];
    const int*   spans = (const int*)d_in[1];
    const int*   mask  = (const int*)d_in[2];
    const float* att_w = (const float*)d_in[3];
    const float* att_b = (const float*)d_in[4];
    const float* ffn_w = (const float*)d_in[5];
    const float* ffn_b = (const float*)d_in[6];
    float*       out   = (float*)d_out;

    cudaFuncSetAttribute(k_gemm, cudaFuncAttributeMaxDynamicSharedMemorySize, SM_GEMM_TOTAL);

    k_wprep<<<NPAD, 192>>>(ffn_w);
    k_logits<<<512, 256>>>(seq, att_w, att_b);
    k_span<<<M_TOTAL, 192>>>(seq, spans, mask);
    k_gemm<<<dim3(64, 2), 512, SM_GEMM_TOTAL>>>(ffn_b, out);
}